// round 16
// baseline (speedup 1.0000x reference)
#include <cuda_runtime.h>
#include <cuda_bf16.h>
#include <cuda_fp16.h>

#define D 512
#define OUTD 128
#define MAXN 50000
#define MAXE 150000
#define BN_EPS 1e-5f

// ---------------- scratch (static device globals; no allocation) ----------------
__device__ __half g_h[(size_t)MAXN * D];    // current node features (fp16)
__device__ float g_hsum[(size_t)MAXN * D];  // hidden_sum accumulator (fp32)
__device__ float g_y[(size_t)MAXN * D];     // gemm1 output
__device__ float g_z[(size_t)MAXN * D];     // gemm2 output
__device__ float g_pq[(size_t)MAXN * 2 * D];// decoder P|Q concat
__device__ float g_stats[2 * 1024];         // slot0: GEMM1 (sum,sumsq), slot1: GEMM2

// CSR graph
__device__ int g_deg[MAXN];
__device__ int g_off[MAXN + 1];
__device__ int g_cur[MAXN];
__device__ int g_adj[2 * MAXE];

// fp16 split pairs: aggregation output z (exact to 2^-22)
__device__ __half g_zh[(size_t)MAXN * D], g_zl[(size_t)MAXN * D];
// fp16 split pairs: decoder hsum
__device__ __half g_hsfh[(size_t)MAXN * D], g_hsfl[(size_t)MAXN * D];
// weights (single fp16, transposed [n][k])
__device__ __half g_l1f[(size_t)4 * D * D];
__device__ __half g_l2f[(size_t)4 * D * D];
__device__ __half g_w1f[(size_t)D * 2 * D];
__device__ __half g_w2f[(size_t)OUTD * D];

// ---------------- PTX helpers (plain compute_100-legal) ----------------
__device__ __forceinline__ unsigned smem_u32(const void* p) {
    unsigned a;
    asm("{ .reg .u64 t; cvta.to.shared.u64 t, %1; cvt.u32.u64 %0, t; }" : "=r"(a) : "l"(p));
    return a;
}
__device__ __forceinline__ void cpasync16(unsigned dst, const void* src) {
    asm volatile("cp.async.cg.shared.global [%0], [%1], 16;" ::"r"(dst), "l"(src));
}
__device__ __forceinline__ void ldm4(unsigned* r, unsigned addr) {
    asm volatile("ldmatrix.sync.aligned.m8n8.x4.shared.b16 {%0,%1,%2,%3}, [%4];"
                 : "=r"(r[0]), "=r"(r[1]), "=r"(r[2]), "=r"(r[3]) : "r"(addr));
}
__device__ __forceinline__ void mma16816h(float* c, const unsigned* a, const unsigned* b) {
    asm volatile(
        "mma.sync.aligned.m16n8k16.row.col.f32.f16.f16.f32 "
        "{%0,%1,%2,%3}, {%4,%5,%6,%7}, {%8,%9}, {%0,%1,%2,%3};"
        : "+f"(c[0]), "+f"(c[1]), "+f"(c[2]), "+f"(c[3])
        : "r"(a[0]), "r"(a[1]), "r"(a[2]), "r"(a[3]), "r"(b[0]), "r"(b[1]));
}
__device__ __forceinline__ void split2h(float a, float b, unsigned& hi, unsigned& lo) {
    __half h0 = __float2half(a);
    __half l0 = __float2half(a - __half2float(h0));
    __half h1 = __float2half(b);
    __half l1 = __float2half(b - __half2float(h1));
    __half2 hp; hp.x = h0; hp.y = h1;
    __half2 lp; lp.x = l0; lp.y = l1;
    hi = *(unsigned*)&hp;
    lo = *(unsigned*)&lp;
}
__device__ __forceinline__ unsigned pack2h(float a, float b) {
    __half2 p; p.x = __float2half(a); p.y = __float2half(b);
    return *(unsigned*)&p;
}

#define EPILOGUE_STORE(BN_, NOUT_)                                             \
    _Pragma("unroll") for (int mf = 0; mf < 2; mf++) {                         \
        const int r0 = bm + wm * 32 + mf * 16 + (lane >> 2);                   \
        _Pragma("unroll") for (int nf = 0; nf < 2 * ((BN_) / 64); nf++) {      \
            const int col = bn + wn * ((BN_) / 4) + nf * 8 + (lane & 3) * 2;   \
            const float* a = acc[mf][nf];                                      \
            _Pragma("unroll") for (int hh = 0; hh < 2; hh++) {                 \
                const int row = r0 + hh * 8;                                   \
                if (row >= M) continue;                                        \
                float2 s = make_float2(a[hh * 2], a[hh * 2 + 1]);              \
                *(float2*)(Cf + (size_t)row * (NOUT_) + col) = s;              \
            }                                                                  \
        }                                                                      \
    }

#define EPILOGUE_STATS(BN_)                                                    \
    _Pragma("unroll") for (int nf = 0; nf < 2 * ((BN_) / 64); nf++) {          \
        float s0 = 0.f, s1 = 0.f, q0 = 0.f, q1 = 0.f;                          \
        _Pragma("unroll") for (int mf = 0; mf < 2; mf++) {                     \
            const int rb = bm + wm * 32 + mf * 16 + (lane >> 2);               \
            _Pragma("unroll") for (int hh = 0; hh < 2; hh++) {                 \
                if (rb + hh * 8 < M) {                                         \
                    float v0 = acc[mf][nf][hh * 2], v1 = acc[mf][nf][hh * 2 + 1];\
                    s0 += v0; q0 += v0 * v0;                                   \
                    s1 += v1; q1 += v1 * v1;                                   \
                }                                                              \
            }                                                                  \
        }                                                                      \
        _Pragma("unroll") for (int o = 4; o < 32; o <<= 1) {                   \
            s0 += __shfl_xor_sync(0xffffffffu, s0, o);                         \
            s1 += __shfl_xor_sync(0xffffffffu, s1, o);                         \
            q0 += __shfl_xor_sync(0xffffffffu, q0, o);                         \
            q1 += __shfl_xor_sync(0xffffffffu, q1, o);                         \
        }                                                                      \
        if ((lane >> 2) == 0) {                                                \
            int col = bn + wn * ((BN_) / 4) + nf * 8 + (lane & 3) * 2;         \
            atomicAdd(&stats_out[col], s0);                                    \
            atomicAdd(&stats_out[col + 1], s1);                                \
            atomicAdd(&stats_out[512 + col], q0);                              \
            atomicAdd(&stats_out[512 + col + 1], q1);                          \
        }                                                                      \
    }

#define ACC_INIT(NB_)                                                          \
    float acc[2][2 * (NB_)][4];                                                \
    _Pragma("unroll") for (int i = 0; i < 2; i++)                              \
        _Pragma("unroll") for (int j = 0; j < 2 * (NB_); j++)                  \
            _Pragma("unroll") for (int q = 0; q < 4; q++) acc[i][j][q] = 0.f;

// 8 mma for one nb-block: 2-pass fp16 (A hi+lo pairs, B single)
#define MMA8(NB_IDX, AH, AL, B0, B1)                                           \
    {                                                                          \
        float* a0 = acc[0][(NB_IDX) * 2];                                      \
        float* a1 = acc[1][(NB_IDX) * 2];                                      \
        float* c0 = acc[0][(NB_IDX) * 2 + 1];                                  \
        float* c1 = acc[1][(NB_IDX) * 2 + 1];                                  \
        mma16816h(a0, AH[0], B0); mma16816h(a1, AH[1], B0);                    \
        mma16816h(c0, AH[0], B1); mma16816h(c1, AH[1], B1);                    \
        mma16816h(a0, AL[0], B0); mma16816h(a1, AL[1], B0);                    \
        mma16816h(c0, AL[0], B1); mma16816h(c1, AL[1], B1);                    \
    }

#define NSTAGE 4

// ---------------- fp16 2-pass GEMM: A = (hi,lo) fp16 pairs in gmem, B single fp16 ----------------
// Used for layer GEMM1 (STATS=1) and decoder PQ (STATS=0). BN=256, 4-stage pipeline.
#define PQ_SMEM (NSTAGE * 40960)  // 163840

template <int STATS>
__global__ __launch_bounds__(512)
void k_mma_f16(const __half* __restrict__ Ah, const __half* __restrict__ Al,
               const __half* __restrict__ Bf,
               float* __restrict__ Cf, int M, int Nout, float* __restrict__ stats_out) {
    constexpr int KTOT = 512, BN = 256, NB = 4, NC = 16;
    constexpr int O_AL = 10240, O_B = 20480, STAGE_BYTES = 40960;

    extern __shared__ __align__(16) char smem[];
    const int tid = threadIdx.x;
    const int wid = tid >> 5, lane = tid & 31;
    const int wm = wid & 3, wn = wid >> 2;
    const int bm = blockIdx.x * 128, bn = blockIdx.y * BN;
    const unsigned sb = smem_u32(smem);

    const int arow = tid >> 2, quad = tid & 3;
    const int grA = min(bm + arow, M - 1);

    ACC_INIT(NB)

#define F16_LOAD(STG, K0)                                                      \
    {                                                                          \
        unsigned st = sb + (STG) * STAGE_BYTES;                                \
        unsigned dsto = arow * 80 + quad * 16;                                 \
        size_t o = (size_t)grA * KTOT + (K0) + quad * 8;                       \
        cpasync16(st + dsto, Ah + o);                                          \
        cpasync16(st + O_AL + dsto, Al + o);                                   \
        _Pragma("unroll") for (int i = 0; i < 2; i++) {                        \
            int brow = arow + i * 128;                                         \
            unsigned bd = brow * 80 + quad * 16;                               \
            size_t ob = (size_t)(bn + brow) * KTOT + (K0) + quad * 8;          \
            cpasync16(st + O_B + bd, Bf + ob);                                 \
        }                                                                      \
    }

#pragma unroll
    for (int p = 0; p < NSTAGE - 1; p++) {
        if (p < NC) F16_LOAD(p, p * 32);
        asm volatile("cp.async.commit_group;");
    }

    int cstg = 0, lstg = NSTAGE - 1;
    for (int c = 0; c < NC; c++) {
        asm volatile("cp.async.wait_group %0;" ::"n"(NSTAGE - 2));
        __syncthreads();
        if (c + NSTAGE - 1 < NC) F16_LOAD(lstg, (c + NSTAGE - 1) * 32);
        asm volatile("cp.async.commit_group;");
        lstg = (lstg + 1 == NSTAGE) ? 0 : lstg + 1;

        const unsigned st = sb + cstg * STAGE_BYTES;
        cstg = (cstg + 1 == NSTAGE) ? 0 : cstg + 1;
#pragma unroll
        for (int ks = 0; ks < 2; ks++) {
            const unsigned koff = ks * 32;
            unsigned ah[2][4], al[2][4];
#pragma unroll
            for (int mf = 0; mf < 2; mf++) {
                unsigned addr = st + (wm * 32 + mf * 16 + (lane & 15)) * 80 +
                                ((lane >> 4) * 16) + koff;
                ldm4(ah[mf], addr);
                ldm4(al[mf], addr + O_AL);
            }
#pragma unroll
            for (int nb = 0; nb < NB; nb++) {
                unsigned addr = st + O_B +
                                (wn * 64 + nb * 16 + (lane & 15)) * 80 +
                                ((lane >> 4) * 16) + koff;
                unsigned bb[4];
                ldm4(bb, addr);
                unsigned b0[2] = {bb[0], bb[2]}, b1[2] = {bb[1], bb[3]};
                MMA8(nb, ah, al, b0, b1)
            }
        }
    }
#undef F16_LOAD

    EPILOGUE_STORE(256, Nout)
    if (STATS) { EPILOGUE_STATS(256) }
}

// ---------------- GEMM2: fused BN-apply loader, 2-pass fp16 ----------------
// A: 2 stages x 20480 (hi +0, lo +10240). B: 4 stages x 20480 at +40960. aff at +122880.
#define BNG_SMEM (2 * 20480 + 4 * 20480 + 4096)  // 126976

__global__ __launch_bounds__(512)
void k_mma_bn(const float* __restrict__ Y,
              const __half* __restrict__ Bf,
              float* __restrict__ Cf, int M,
              const float* __restrict__ stats_in, const float* __restrict__ gamma,
              const float* __restrict__ beta, float* __restrict__ stats_out) {
    constexpr int KTOT = 512, BN = 256, NB = 4, NC = 16;
    constexpr int O_B = 40960;
    constexpr int O_AFF = 122880;
    extern __shared__ __align__(16) char smem[];
    float* s_aff = (float*)(smem + O_AFF);
    const int tid = threadIdx.x;
    const int wid = tid >> 5, lane = tid & 31;
    const int wm = wid & 3, wn = wid >> 2;
    const int bm = blockIdx.x * 128, bn = blockIdx.y * BN;
    const unsigned sb = smem_u32(smem);

    if (tid < 512) {
        float inv = 1.f / (float)M;
        float m = stats_in[tid] * inv;
        float var = stats_in[512 + tid] * inv - m * m;
        float sc = gamma[tid] * rsqrtf(var + BN_EPS);
        s_aff[tid] = sc;
        s_aff[512 + tid] = beta[tid] - m * sc;
    }

    const int arow = tid >> 2, quad = tid & 3;
    const int grA = min(bm + arow, M - 1);

    ACC_INIT(NB)

#define BNG_LOADB(STG, K0)                                                     \
    {                                                                          \
        unsigned st = sb + O_B + (STG) * 20480;                                \
        _Pragma("unroll") for (int i = 0; i < 2; i++) {                        \
            int brow = arow + i * 128;                                         \
            unsigned bd = brow * 80 + quad * 16;                               \
            size_t ob = (size_t)(bn + brow) * KTOT + (K0) + quad * 8;          \
            cpasync16(st + bd, Bf + ob);                                       \
        }                                                                      \
    }
#define BNG_LDGA(K0)                                                           \
    {                                                                          \
        const float4* yp = (const float4*)(Y + (size_t)grA * KTOT + (K0) + quad * 8);\
        ya[0] = __ldg(yp); ya[1] = __ldg(yp + 1);                              \
    }

    float4 ya[2];
    BNG_LDGA(0);
    BNG_LOADB(0, 0);
    asm volatile("cp.async.commit_group;");
    BNG_LOADB(1, 32);
    asm volatile("cp.async.commit_group;");
    BNG_LOADB(2, 64);
    asm volatile("cp.async.commit_group;");
    __syncthreads();  // s_aff visible

    for (int c = 0; c < NC; c++) {
        // STS A(c): affine + relu + exact fp16 split (stage c&1)
        {
            unsigned hi[4], lo[4];
            const int kb = c * 32 + quad * 8;
#pragma unroll
            for (int j = 0; j < 2; j++) {
                float4 y = ya[j];
                const int k = kb + j * 4;
                float x0 = fmaxf(y.x * s_aff[k + 0] + s_aff[512 + k + 0], 0.f);
                float x1 = fmaxf(y.y * s_aff[k + 1] + s_aff[512 + k + 1], 0.f);
                float x2 = fmaxf(y.z * s_aff[k + 2] + s_aff[512 + k + 2], 0.f);
                float x3 = fmaxf(y.w * s_aff[k + 3] + s_aff[512 + k + 3], 0.f);
                split2h(x0, x1, hi[j * 2], lo[j * 2]);
                split2h(x2, x3, hi[j * 2 + 1], lo[j * 2 + 1]);
            }
            char* ad = smem + (c & 1) * 20480 + arow * 80 + quad * 16;
            *(uint4*)ad = make_uint4(hi[0], hi[1], hi[2], hi[3]);
            *(uint4*)(ad + 10240) = make_uint4(lo[0], lo[1], lo[2], lo[3]);
        }
        asm volatile("cp.async.wait_group 2;");
        __syncthreads();
        if (c + 1 < NC) BNG_LDGA((c + 1) * 32);
        if (c + 3 < NC) BNG_LOADB((c + 3) & 3, (c + 3) * 32);
        asm volatile("cp.async.commit_group;");

        const unsigned ast = sb + (c & 1) * 20480;
        const unsigned bst = sb + O_B + (c & 3) * 20480;
#pragma unroll
        for (int ks = 0; ks < 2; ks++) {
            const unsigned koff = ks * 32;
            unsigned ah[2][4], al[2][4];
#pragma unroll
            for (int mf = 0; mf < 2; mf++) {
                unsigned addr = ast + (wm * 32 + mf * 16 + (lane & 15)) * 80 +
                                ((lane >> 4) * 16) + koff;
                ldm4(ah[mf], addr);
                ldm4(al[mf], addr + 10240);
            }
#pragma unroll
            for (int nb = 0; nb < NB; nb++) {
                unsigned addr = bst + (wn * 64 + nb * 16 + (lane & 15)) * 80 +
                                ((lane >> 4) * 16) + koff;
                unsigned bb[4];
                ldm4(bb, addr);
                unsigned b0[2] = {bb[0], bb[2]}, b1[2] = {bb[1], bb[3]};
                MMA8(nb, ah, al, b0, b1)
            }
        }
    }
#undef BNG_LOADB
#undef BNG_LDGA

    const int Nout = 512;
    EPILOGUE_STORE(256, Nout)
    EPILOGUE_STATS(256)
}

// ---------------- decoder final GEMM: fused edge loader, 2-pass fp16 ----------------
// A: 2 stages x 20480. B: 4 stages x 10240 at +40960.
#define DEC_SMEM (2 * 20480 + 4 * 10240)  // 81920

__global__ __launch_bounds__(512)
void k_dec(const float* __restrict__ PQ,
           const __half* __restrict__ Bf,
           float* __restrict__ Cf, int M,
           const int* __restrict__ gu, const int* __restrict__ gv,
           const float* __restrict__ bias1, const float* __restrict__ bias2) {
    constexpr int KTOT = 512, NB = 2, NC = 16;
    extern __shared__ __align__(16) char smem[];
    __shared__ int s_u[128], s_v[128];
    const int tid = threadIdx.x;
    const int wid = tid >> 5, lane = tid & 31;
    const int wm = wid & 3, wn = wid >> 2;
    const int bm = blockIdx.x * 128;
    const unsigned sb = smem_u32(smem);

    if (tid < 128) {
        int e = min(bm + tid, M - 1);
        s_u[tid] = gu[e];
        s_v[tid] = gv[e];
    }
    __syncthreads();

    const int arow = tid >> 2, quad = tid & 3;
    const size_t prow = (size_t)s_u[arow] * 1024;
    const size_t qrow = (size_t)s_v[arow] * 1024 + 512;

    ACC_INIT(NB)

#define DEC_LOADB(STG, K0)                                                     \
    {                                                                          \
        unsigned st = sb + 40960 + (STG) * 10240;                              \
        unsigned bd = arow * 80 + quad * 16;                                   \
        size_t ob = (size_t)arow * KTOT + (K0) + quad * 8;                     \
        cpasync16(st + bd, Bf + ob);                                           \
    }
#define DEC_LDGA(K0)                                                           \
    {                                                                          \
        const float4* pp = (const float4*)(PQ + prow + (K0) + quad * 8);       \
        const float4* qq = (const float4*)(PQ + qrow + (K0) + quad * 8);       \
        pa[0] = __ldg(pp); pa[1] = __ldg(pp + 1);                              \
        qa[0] = __ldg(qq); qa[1] = __ldg(qq + 1);                              \
    }

    float4 pa[2], qa[2];
    DEC_LDGA(0);
    DEC_LOADB(0, 0);
    asm volatile("cp.async.commit_group;");
    DEC_LOADB(1, 32);
    asm volatile("cp.async.commit_group;");
    DEC_LOADB(2, 64);
    asm volatile("cp.async.commit_group;");

    for (int c = 0; c < NC; c++) {
        {
            unsigned hi[4], lo[4];
            const float* b1 = bias1 + c * 32 + quad * 8;
#pragma unroll
            for (int j = 0; j < 2; j++) {
                float4 p = pa[j], q = qa[j];
                float4 bb = *(const float4*)(b1 + j * 4);
                float x0 = fmaxf(p.x + q.x + bb.x, 0.f);
                float x1 = fmaxf(p.y + q.y + bb.y, 0.f);
                float x2 = fmaxf(p.z + q.z + bb.z, 0.f);
                float x3 = fmaxf(p.w + q.w + bb.w, 0.f);
                split2h(x0, x1, hi[j * 2], lo[j * 2]);
                split2h(x2, x3, hi[j * 2 + 1], lo[j * 2 + 1]);
            }
            char* ad = smem + (c & 1) * 20480 + arow * 80 + quad * 16;
            *(uint4*)ad = make_uint4(hi[0], hi[1], hi[2], hi[3]);
            *(uint4*)(ad + 10240) = make_uint4(lo[0], lo[1], lo[2], lo[3]);
        }
        asm volatile("cp.async.wait_group 2;");
        __syncthreads();
        if (c + 1 < NC) DEC_LDGA((c + 1) * 32);
        if (c + 3 < NC) DEC_LOADB((c + 3) & 3, (c + 3) * 32);
        asm volatile("cp.async.commit_group;");

        const unsigned ast = sb + (c & 1) * 20480;
        const unsigned bst = sb + 40960 + (c & 3) * 10240;
#pragma unroll
        for (int ks = 0; ks < 2; ks++) {
            const unsigned koff = ks * 32;
            unsigned ah[2][4], al[2][4];
#pragma unroll
            for (int mf = 0; mf < 2; mf++) {
                unsigned addr = ast + (wm * 32 + mf * 16 + (lane & 15)) * 80 +
                                ((lane >> 4) * 16) + koff;
                ldm4(ah[mf], addr);
                ldm4(al[mf], addr + 10240);
            }
#pragma unroll
            for (int nb = 0; nb < NB; nb++) {
                unsigned addr = bst + (wn * 32 + nb * 16 + (lane & 15)) * 80 +
                                ((lane >> 4) * 16) + koff;
                unsigned bb[4];
                ldm4(bb, addr);
                unsigned b0[2] = {bb[0], bb[2]}, b1[2] = {bb[1], bb[3]};
                MMA8(nb, ah, al, b0, b1)
            }
        }
    }
#undef DEC_LOADB
#undef DEC_LDGA

#pragma unroll
    for (int mf = 0; mf < 2; mf++) {
        const int r0 = bm + wm * 32 + mf * 16 + (lane >> 2);
#pragma unroll
        for (int nf = 0; nf < 2 * NB; nf++) {
            const int col = wn * 32 + nf * 8 + (lane & 3) * 2;
#pragma unroll
            for (int hh = 0; hh < 2; hh++) {
                const int row = r0 + hh * 8;
                if (row >= M) continue;
                float2 s = make_float2(acc[mf][nf][hh * 2] + bias2[col],
                                       acc[mf][nf][hh * 2 + 1] + bias2[col + 1]);
                *(float2*)(Cf + (size_t)row * OUTD + col) = s;
            }
        }
    }
}

// ---------------- CSR build ----------------
__global__ void k_zerodeg(int Nn) {
    int i = blockIdx.x * blockDim.x + threadIdx.x;
    if (i < Nn) g_deg[i] = 0;
}
__global__ void k_deg(const int* __restrict__ u, const int* __restrict__ v, int E) {
    int e = blockIdx.x * blockDim.x + threadIdx.x;
    if (e >= E) return;
    atomicAdd(&g_deg[u[e]], 1);
    atomicAdd(&g_deg[v[e]], 1);
}
__global__ void k_scan(int Nn) {
    __shared__ int warpsum[32];
    __shared__ int s_carry;
    const int tid = threadIdx.x, lane = tid & 31, w = tid >> 5;
    if (tid == 0) s_carry = 0;
    __syncthreads();
    for (int base = 0; base < Nn; base += 1024) {
        int i = base + tid;
        int v = (i < Nn) ? g_deg[i] : 0;
        int x = v;
#pragma unroll
        for (int o = 1; o < 32; o <<= 1) {
            int t = __shfl_up_sync(0xffffffffu, x, o);
            if (lane >= o) x += t;
        }
        if (lane == 31) warpsum[w] = x;
        __syncthreads();
        if (w == 0) {
            int s = warpsum[lane];
#pragma unroll
            for (int o = 1; o < 32; o <<= 1) {
                int t = __shfl_up_sync(0xffffffffu, s, o);
                if (lane >= o) s += t;
            }
            warpsum[lane] = s;
        }
        __syncthreads();
        int incl = x + (w > 0 ? warpsum[w - 1] : 0) + s_carry;
        if (i < Nn) {
            int excl = incl - v;
            g_off[i] = excl;
            g_cur[i] = excl;
        }
        __syncthreads();
        if (tid == 1023) s_carry = incl;
        __syncthreads();
    }
    if (tid == 0) g_off[Nn] = s_carry;
}
__global__ void k_fill(const int* __restrict__ u, const int* __restrict__ v, int E) {
    int e = blockIdx.x * blockDim.x + threadIdx.x;
    if (e >= E) return;
    int a = u[e], b = v[e];
    int p = atomicAdd(&g_cur[b], 1);
    g_adj[p] = a;
    int q = atomicAdd(&g_cur[a], 1);
    g_adj[q] = b;
}

// ---------------- aggregation: z = 2h + sum_{nb} h[nb] (h fp16) -> fp16 pairs ----------------
// Also zeroes both BN stats slots (block 0) — safe: runs strictly between the
// previous layer's stats read and this layer's GEMM1 stats write.
__global__ void k_agg(int Nn) {
    if (blockIdx.x == 0) {
#pragma unroll
        for (int t = threadIdx.x; t < 2048; t += 256) g_stats[t] = 0.f;
    }
    const int w = threadIdx.x >> 5;               // 0..7
    const int node = blockIdx.x * 4 + (w >> 1);
    if (node >= Nn) return;
    const int lane = threadIdx.x & 31;
    const int ci = (w & 1) * 32 + lane;           // uint4 index 0..63 (8 halves each)

    float acc[8];
    {
        uint4 t = ((const uint4*)(g_h + (size_t)node * D))[ci];
        const __half2* hh = (const __half2*)&t;
#pragma unroll
        for (int j = 0; j < 4; j++) {
            float2 f = __half22float2(hh[j]);
            acc[j * 2] = 2.f * f.x;
            acc[j * 2 + 1] = 2.f * f.y;
        }
    }
    const int e1 = g_off[node + 1];
    int e = g_off[node];
    if (e < e1) {
        uint4 cur = ((const uint4*)(g_h + (size_t)__ldg(&g_adj[e]) * D))[ci];
        for (++e; e < e1; ++e) {
            uint4 nxt = ((const uint4*)(g_h + (size_t)__ldg(&g_adj[e]) * D))[ci];
            const __half2* hh = (const __half2*)&cur;
#pragma unroll
            for (int j = 0; j < 4; j++) {
                float2 f = __half22float2(hh[j]);
                acc[j * 2] += f.x;
                acc[j * 2 + 1] += f.y;
            }
            cur = nxt;
        }
        const __half2* hh = (const __half2*)&cur;
#pragma unroll
        for (int j = 0; j < 4; j++) {
            float2 f = __half22float2(hh[j]);
            acc[j * 2] += f.x;
            acc[j * 2 + 1] += f.y;
        }
    }
    {
        unsigned hi[4], lo[4];
        split2h(acc[0], acc[1], hi[0], lo[0]);
        split2h(acc[2], acc[3], hi[1], lo[1]);
        split2h(acc[4], acc[5], hi[2], lo[2]);
        split2h(acc[6], acc[7], hi[3], lo[3]);
        size_t o = (size_t)node * D + (size_t)ci * 8;
        *(uint4*)(g_zh + o) = make_uint4(hi[0], hi[1], hi[2], hi[3]);
        *(uint4*)(g_zl + o) = make_uint4(lo[0], lo[1], lo[2], lo[3]);
    }
}

// ---------------- elementwise kernels ----------------
__global__ void k_gather(const int* __restrict__ ids, const float* __restrict__ emb, int Nn) {
    int idx = blockIdx.x * blockDim.x + threadIdx.x;
    int row = idx >> 7;
    if (row >= Nn) return;
    int c = (idx & 127) << 2;
    float4 val = *(const float4*)(emb + (size_t)ids[row] * D + c);
    size_t o = (size_t)row * D + c;
    ((unsigned*)(g_h + o))[0] = pack2h(val.x, val.y);
    ((unsigned*)(g_h + o))[1] = pack2h(val.z, val.w);
    *(float4*)(g_hsum + o) = val;
}

// merged weight conversion: all matrices, one launch.
// seg0: lin1 (4x[512,512]) -> l1f ; seg1: lin2 -> l2f ;
// seg2: W1 (2x[512,512] halves) -> w1f ; seg3: W2 [512,128] -> w2f.
#define WCVT_TOTAL (1048576 + 1048576 + 524288 + 65536)
__global__ void k_wcvt(const float* __restrict__ lin1, const float* __restrict__ lin2,
                       const float* __restrict__ W1, const float* __restrict__ W2) {
    int idx = blockIdx.x * blockDim.x + threadIdx.x;
    if (idx >= WCVT_TOTAL) return;
    if (idx < 1048576) {
        int local = idx;
        int mi = local >> 18, within = local & 262143;
        int n = within >> 9, k = within & 511;
        g_l1f[idx] = __float2half(lin1[(size_t)mi * 262144 + (size_t)k * 512 + n]);
    } else if (idx < 2097152) {
        int local = idx - 1048576;
        int mi = local >> 18, within = local & 262143;
        int n = within >> 9, k = within & 511;
        g_l2f[local] = __float2half(lin2[(size_t)mi * 262144 + (size_t)k * 512 + n]);
    } else if (idx < 2621440) {
        int local = idx - 2097152;
        int half = local >> 18, within = local & 262143;
        int n = within >> 9, k = within & 511;
        g_w1f[local] = __float2half(W1[(size_t)half * 262144 + (size_t)k * 512 + n]);
    } else {
        int local = idx - 2621440;
        int n = local >> 9, k = local & 511;
        g_w2f[local] = __float2half(W2[(size_t)k * OUTD + n]);
    }
}

// h = relu(affine(Y2)); hsum += h ; aff computed in-block from stats slot
// LAST=0: write h fp16 + hsum fp32.  LAST=1: write (hsum+h) as fp16 pairs only.
template <int LAST>
__global__ void k_bnrelu_acc(const float* __restrict__ Y2,
                             const float* __restrict__ stats,
                             const float* __restrict__ gamma,
                             const float* __restrict__ beta, int Nn) {
    __shared__ float s_aff[1024];
    int tid = threadIdx.x;
    {
        float inv = 1.f / (float)Nn;
#pragma unroll
        for (int j = tid; j < 512; j += 256) {
            float m = stats[j] * inv;
            float var = stats[512 + j] * inv - m * m;
            float sc = gamma[j] * rsqrtf(var + BN_EPS);
            s_aff[j] = sc;
            s_aff[512 + j] = beta[j] - m * sc;
        }
    }
    __syncthreads();
    int idx = blockIdx.x * blockDim.x + tid;
    if (idx >= Nn * 128) return;
    int c = (idx & 127) << 2;
    float4 v = *(const float4*)(Y2 + (size_t)idx * 4);
    v.x = fmaxf(v.x * s_aff[c + 0] + s_aff[512 + c + 0], 0.f);
    v.y = fmaxf(v.y * s_aff[c + 1] + s_aff[512 + c + 1], 0.f);
    v.z = fmaxf(v.z * s_aff[c + 2] + s_aff[512 + c + 2], 0.f);
    v.w = fmaxf(v.w * s_aff[c + 3] + s_aff[512 + c + 3], 0.f);
    float4 hs = *(const float4*)(g_hsum + (size_t)idx * 4);
    hs.x += v.x; hs.y += v.y; hs.z += v.z; hs.w += v.w;
    if (!LAST) {
        ((unsigned*)(g_h + (size_t)idx * 4))[0] = pack2h(v.x, v.y);
        ((unsigned*)(g_h + (size_t)idx * 4))[1] = pack2h(v.z, v.w);
        *(float4*)(g_hsum + (size_t)idx * 4) = hs;
    } else {
        unsigned h0, l0, h1, l1;
        split2h(hs.x, hs.y, h0, l0);
        split2h(hs.z, hs.w, h1, l1);
        ((unsigned*)(g_hsfh + (size_t)idx * 4))[0] = h0;
        ((unsigned*)(g_hsfh + (size_t)idx * 4))[1] = h1;
        ((unsigned*)(g_hsfl + (size_t)idx * 4))[0] = l0;
        ((unsigned*)(g_hsfl + (size_t)idx * 4))[1] = l1;
    }
}

// ---------------- launch ----------------
extern "C" void kernel_launch(void* const* d_in, const int* in_sizes, int n_in,
                              void* d_out, int out_size) {
    const int* h_ids = (const int*)d_in[0];
    const int* u     = (const int*)d_in[1];
    const int* v     = (const int*)d_in[2];
    const float* emb   = (const float*)d_in[3];
    const float* lin1  = (const float*)d_in[4];
    const float* lin2  = (const float*)d_in[5];
    const float* bn1_g = (const float*)d_in[6];
    const float* bn1_b = (const float*)d_in[7];
    const float* bn2_g = (const float*)d_in[8];
    const float* bn2_b = (const float*)d_in[9];
    const float* W1_w  = (const float*)d_in[10];
    const float* W1_b  = (const float*)d_in[11];
    const float* W2_w  = (const float*)d_in[12];
    const float* W2_b  = (const float*)d_in[13];
    float* out = (float*)d_out;

    const int N = in_sizes[0];
    const int E = in_sizes[1];
    const int L = in_sizes[4] / (D * D);

    static int s_attr = 0;
    if (!s_attr) {
        cudaFuncSetAttribute(k_mma_f16<0>, cudaFuncAttributeMaxDynamicSharedMemorySize, PQ_SMEM);
        cudaFuncSetAttribute(k_mma_f16<1>, cudaFuncAttributeMaxDynamicSharedMemorySize, PQ_SMEM);
        cudaFuncSetAttribute(k_mma_bn, cudaFuncAttributeMaxDynamicSharedMemorySize, BNG_SMEM);
        cudaFuncSetAttribute(k_dec, cudaFuncAttributeMaxDynamicSharedMemorySize, DEC_SMEM);
        s_attr = 1;
    }

    float *dg_z, *dg_y, *dg_pq, *dg_stats;
    cudaGetSymbolAddress((void**)&dg_z, g_z);
    cudaGetSymbolAddress((void**)&dg_y, g_y);
    cudaGetSymbolAddress((void**)&dg_pq, g_pq);
    cudaGetSymbolAddress((void**)&dg_stats, g_stats);
    __half *zh, *zl, *hsfh, *hsfl, *l1f, *l2f, *w1f, *w2f;
    cudaGetSymbolAddress((void**)&zh, g_zh);  cudaGetSymbolAddress((void**)&zl, g_zl);
    cudaGetSymbolAddress((void**)&hsfh, g_hsfh); cudaGetSymbolAddress((void**)&hsfl, g_hsfl);
    cudaGetSymbolAddress((void**)&l1f, g_l1f);
    cudaGetSymbolAddress((void**)&l2f, g_l2f);
    cudaGetSymbolAddress((void**)&w1f, g_w1f);
    cudaGetSymbolAddress((void**)&w2f, g_w2f);

    const int ew = N * 128, ewB = (ew + 255) / 256;
    const int mtiles = (N + 127) / 128;
    const int etiles = (E + 127) / 128;
    const int edB = (E + 255) / 256;
    const int ndB = (N + 255) / 256;
    const int aggB = (N + 3) / 4;

    // merged weight conversion (one launch)
    k_wcvt<<<(WCVT_TOTAL + 255) / 256, 256>>>(lin1, lin2, W1_w, W2_w);

    // h = emb[h_ids] (fp16); hidden_sum = h (fp32)
    k_gather<<<ewB, 256>>>(h_ids, emb, N);

    // CSR build (once)
    k_zerodeg<<<ndB, 256>>>(N);
    k_deg<<<edB, 256>>>(u, v, E);
    k_scan<<<1, 1024>>>(N);
    k_fill<<<edB, 256>>>(u, v, E);

    for (int i = 0; i < L; i++) {
        // z = 2h + neighbor sums -> fp16 pairs ; block 0 zeroes both stats slots
        k_agg<<<aggB, 256>>>(N);
        // y = z @ lin1[i]  (2-pass fp16, stats -> slot0)
        k_mma_f16<1><<<dim3(mtiles, 2), 512, PQ_SMEM>>>(
            zh, zl, l1f + (size_t)i * D * D, dg_y, N, D, dg_stats);
        // z(out) = relu(bn1(y)) @ lin2[i]  (fused BN loader, 2-pass fp16; stats -> slot1)
        k_mma_bn<<<dim3(mtiles, 2), 512, BNG_SMEM>>>(
            dg_y, l2f + (size_t)i * D * D, dg_z, N,
            dg_stats, bn1_g + (size_t)i * D, bn1_b + (size_t)i * D,
            dg_stats + 1024);
        // h = relu(bn2(z)); hsum += h  (aff computed in-block from slot1)
        if (i == L - 1)
            k_bnrelu_acc<1><<<ewB, 256>>>(dg_z, dg_stats + 1024,
                bn2_g + (size_t)i * D, bn2_b + (size_t)i * D, N);
        else
            k_bnrelu_acc<0><<<ewB, 256>>>(dg_z, dg_stats + 1024,
                bn2_g + (size_t)i * D, bn2_b + (size_t)i * D, N);
    }

    // decoder: [P|Q] = hsum_fp16pairs @ fp16(W1t)^T  (2-pass fp16, Nout=1024)
    k_mma_f16<0><<<dim3(mtiles, 4), 512, PQ_SMEM>>>(
        hsfh, hsfl, w1f, dg_pq, N, 2 * D, nullptr);
    // out = relu(P[u]+Q[v]+b1) @ fp16(W2)^T + b2  (fused edge loader, 2-pass fp16)
    k_dec<<<etiles, 512, DEC_SMEM>>>(dg_pq, w2f, out, E, u, v, W1_b, W2_b);
}

// round 17
// speedup vs baseline: 1.0133x; 1.0133x over previous
#include <cuda_runtime.h>
#include <cuda_bf16.h>
#include <cuda_fp16.h>

#define D 512
#define OUTD 128
#define MAXN 50000
#define MAXE 150000
#define BN_EPS 1e-5f
#define ND ((size_t)MAXN * D)

// ---------------- scratch (static device globals; no allocation) ----------------
__device__ __half g_hl[5 * ND];             // h slots: 0=emb, 1..4=layer outputs (fp16)
__device__ float g_y[ND];                   // gemm1 output
__device__ float g_z[ND];                   // gemm2 output
__device__ float g_pq[2 * ND];              // decoder P|Q concat
__device__ float g_stats[2 * 1024];         // slot0: GEMM1 (sum,sumsq), slot1: GEMM2

// CSR graph
__device__ int g_deg[MAXN];
__device__ int g_off[MAXN + 1];
__device__ int g_cur[MAXN];
__device__ int g_adj[2 * MAXE];

// fp16 split pairs: aggregation output z (exact to 2^-22)
__device__ __half g_zh[ND], g_zl[ND];
// fp16 split pairs: decoder hsum
__device__ __half g_hsfh[ND], g_hsfl[ND];
// weights (single fp16, transposed [n][k])
__device__ __half g_l1f[(size_t)4 * D * D];
__device__ __half g_l2f[(size_t)4 * D * D];
__device__ __half g_w1f[(size_t)D * 2 * D];
__device__ __half g_w2f[(size_t)OUTD * D];

// ---------------- PTX helpers (plain compute_100-legal) ----------------
__device__ __forceinline__ unsigned smem_u32(const void* p) {
    unsigned a;
    asm("{ .reg .u64 t; cvta.to.shared.u64 t, %1; cvt.u32.u64 %0, t; }" : "=r"(a) : "l"(p));
    return a;
}
__device__ __forceinline__ void cpasync16(unsigned dst, const void* src) {
    asm volatile("cp.async.cg.shared.global [%0], [%1], 16;" ::"r"(dst), "l"(src));
}
__device__ __forceinline__ void ldm4(unsigned* r, unsigned addr) {
    asm volatile("ldmatrix.sync.aligned.m8n8.x4.shared.b16 {%0,%1,%2,%3}, [%4];"
                 : "=r"(r[0]), "=r"(r[1]), "=r"(r[2]), "=r"(r[3]) : "r"(addr));
}
__device__ __forceinline__ void mma16816h(float* c, const unsigned* a, const unsigned* b) {
    asm volatile(
        "mma.sync.aligned.m16n8k16.row.col.f32.f16.f16.f32 "
        "{%0,%1,%2,%3}, {%4,%5,%6,%7}, {%8,%9}, {%0,%1,%2,%3};"
        : "+f"(c[0]), "+f"(c[1]), "+f"(c[2]), "+f"(c[3])
        : "r"(a[0]), "r"(a[1]), "r"(a[2]), "r"(a[3]), "r"(b[0]), "r"(b[1]));
}
__device__ __forceinline__ void split2h(float a, float b, unsigned& hi, unsigned& lo) {
    __half h0 = __float2half(a);
    __half l0 = __float2half(a - __half2float(h0));
    __half h1 = __float2half(b);
    __half l1 = __float2half(b - __half2float(h1));
    __half2 hp; hp.x = h0; hp.y = h1;
    __half2 lp; lp.x = l0; lp.y = l1;
    hi = *(unsigned*)&hp;
    lo = *(unsigned*)&lp;
}
__device__ __forceinline__ unsigned pack2h(float a, float b) {
    __half2 p; p.x = __float2half(a); p.y = __float2half(b);
    return *(unsigned*)&p;
}

#define EPILOGUE_STORE(BN_, NOUT_)                                             \
    _Pragma("unroll") for (int mf = 0; mf < 2; mf++) {                         \
        const int r0 = bm + wm * 32 + mf * 16 + (lane >> 2);                   \
        _Pragma("unroll") for (int nf = 0; nf < 2 * ((BN_) / 64); nf++) {      \
            const int col = bn + wn * ((BN_) / 4) + nf * 8 + (lane & 3) * 2;   \
            const float* a = acc[mf][nf];                                      \
            _Pragma("unroll") for (int hh = 0; hh < 2; hh++) {                 \
                const int row = r0 + hh * 8;                                   \
                if (row >= M) continue;                                        \
                float2 s = make_float2(a[hh * 2], a[hh * 2 + 1]);              \
                *(float2*)(Cf + (size_t)row * (NOUT_) + col) = s;              \
            }                                                                  \
        }                                                                      \
    }

#define EPILOGUE_STATS(BN_)                                                    \
    _Pragma("unroll") for (int nf = 0; nf < 2 * ((BN_) / 64); nf++) {          \
        float s0 = 0.f, s1 = 0.f, q0 = 0.f, q1 = 0.f;                          \
        _Pragma("unroll") for (int mf = 0; mf < 2; mf++) {                     \
            const int rb = bm + wm * 32 + mf * 16 + (lane >> 2);               \
            _Pragma("unroll") for (int hh = 0; hh < 2; hh++) {                 \
                if (rb + hh * 8 < M) {                                         \
                    float v0 = acc[mf][nf][hh * 2], v1 = acc[mf][nf][hh * 2 + 1];\
                    s0 += v0; q0 += v0 * v0;                                   \
                    s1 += v1; q1 += v1 * v1;                                   \
                }                                                              \
            }                                                                  \
        }                                                                      \
        _Pragma("unroll") for (int o = 4; o < 32; o <<= 1) {                   \
            s0 += __shfl_xor_sync(0xffffffffu, s0, o);                         \
            s1 += __shfl_xor_sync(0xffffffffu, s1, o);                         \
            q0 += __shfl_xor_sync(0xffffffffu, q0, o);                         \
            q1 += __shfl_xor_sync(0xffffffffu, q1, o);                         \
        }                                                                      \
        if ((lane >> 2) == 0) {                                                \
            int col = bn + wn * ((BN_) / 4) + nf * 8 + (lane & 3) * 2;         \
            atomicAdd(&stats_out[col], s0);                                    \
            atomicAdd(&stats_out[col + 1], s1);                                \
            atomicAdd(&stats_out[512 + col], q0);                              \
            atomicAdd(&stats_out[512 + col + 1], q1);                          \
        }                                                                      \
    }

#define ACC_INIT(NB_)                                                          \
    float acc[2][2 * (NB_)][4];                                                \
    _Pragma("unroll") for (int i = 0; i < 2; i++)                              \
        _Pragma("unroll") for (int j = 0; j < 2 * (NB_); j++)                  \
            _Pragma("unroll") for (int q = 0; q < 4; q++) acc[i][j][q] = 0.f;

// 8 mma for one nb-block: 2-pass fp16 (A hi+lo pairs, B single)
#define MMA8(NB_IDX, AH, AL, B0, B1)                                           \
    {                                                                          \
        float* a0 = acc[0][(NB_IDX) * 2];                                      \
        float* a1 = acc[1][(NB_IDX) * 2];                                      \
        float* c0 = acc[0][(NB_IDX) * 2 + 1];                                  \
        float* c1 = acc[1][(NB_IDX) * 2 + 1];                                  \
        mma16816h(a0, AH[0], B0); mma16816h(a1, AH[1], B0);                    \
        mma16816h(c0, AH[0], B1); mma16816h(c1, AH[1], B1);                    \
        mma16816h(a0, AL[0], B0); mma16816h(a1, AL[1], B0);                    \
        mma16816h(c0, AL[0], B1); mma16816h(c1, AL[1], B1);                    \
    }

#define NSTAGE 3

// ---------------- fp16 2-pass GEMM: A = (hi,lo) fp16 pairs in gmem, B single fp16 ----------------
// Used for layer GEMM1 (STATS=1) and decoder PQ (STATS=0). BN=256, 3-stage pipeline.
#define PQ_SMEM (NSTAGE * 40960)  // 122880

template <int STATS>
__global__ __launch_bounds__(512)
void k_mma_f16(const __half* __restrict__ Ah, const __half* __restrict__ Al,
               const __half* __restrict__ Bf,
               float* __restrict__ Cf, int M, int Nout, float* __restrict__ stats_out) {
    constexpr int KTOT = 512, BN = 256, NB = 4, NC = 16;
    constexpr int O_AL = 10240, O_B = 20480, STAGE_BYTES = 40960;

    extern __shared__ __align__(16) char smem[];
    const int tid = threadIdx.x;
    const int wid = tid >> 5, lane = tid & 31;
    const int wm = wid & 3, wn = wid >> 2;
    const int bm = blockIdx.x * 128, bn = blockIdx.y * BN;
    const unsigned sb = smem_u32(smem);

    const int arow = tid >> 2, quad = tid & 3;
    const int grA = min(bm + arow, M - 1);

    ACC_INIT(NB)

#define F16_LOAD(STG, K0)                                                      \
    {                                                                          \
        unsigned st = sb + (STG) * STAGE_BYTES;                                \
        unsigned dsto = arow * 80 + quad * 16;                                 \
        size_t o = (size_t)grA * KTOT + (K0) + quad * 8;                       \
        cpasync16(st + dsto, Ah + o);                                          \
        cpasync16(st + O_AL + dsto, Al + o);                                   \
        _Pragma("unroll") for (int i = 0; i < 2; i++) {                        \
            int brow = arow + i * 128;                                         \
            unsigned bd = brow * 80 + quad * 16;                               \
            size_t ob = (size_t)(bn + brow) * KTOT + (K0) + quad * 8;          \
            cpasync16(st + O_B + bd, Bf + ob);                                 \
        }                                                                      \
    }

#pragma unroll
    for (int p = 0; p < NSTAGE - 1; p++) {
        if (p < NC) F16_LOAD(p, p * 32);
        asm volatile("cp.async.commit_group;");
    }

    int cstg = 0, lstg = NSTAGE - 1;
    for (int c = 0; c < NC; c++) {
        asm volatile("cp.async.wait_group %0;" ::"n"(NSTAGE - 2));
        __syncthreads();
        if (c + NSTAGE - 1 < NC) F16_LOAD(lstg, (c + NSTAGE - 1) * 32);
        asm volatile("cp.async.commit_group;");
        lstg = (lstg + 1 == NSTAGE) ? 0 : lstg + 1;

        const unsigned st = sb + cstg * STAGE_BYTES;
        cstg = (cstg + 1 == NSTAGE) ? 0 : cstg + 1;
#pragma unroll
        for (int ks = 0; ks < 2; ks++) {
            const unsigned koff = ks * 32;
            unsigned ah[2][4], al[2][4];
#pragma unroll
            for (int mf = 0; mf < 2; mf++) {
                unsigned addr = st + (wm * 32 + mf * 16 + (lane & 15)) * 80 +
                                ((lane >> 4) * 16) + koff;
                ldm4(ah[mf], addr);
                ldm4(al[mf], addr + O_AL);
            }
#pragma unroll
            for (int nb = 0; nb < NB; nb++) {
                unsigned addr = st + O_B +
                                (wn * 64 + nb * 16 + (lane & 15)) * 80 +
                                ((lane >> 4) * 16) + koff;
                unsigned bb[4];
                ldm4(bb, addr);
                unsigned b0[2] = {bb[0], bb[2]}, b1[2] = {bb[1], bb[3]};
                MMA8(nb, ah, al, b0, b1)
            }
        }
    }
#undef F16_LOAD

    EPILOGUE_STORE(256, Nout)
    if (STATS) { EPILOGUE_STATS(256) }
}

// ---------------- GEMM2: fused BN-apply loader, 2-pass fp16 ----------------
// A: 2 stages x 20480 (hi +0, lo +10240). B: 3 stages x 20480 at +40960. aff at +102400.
#define BNG_SMEM (2 * 20480 + 3 * 20480 + 4096)  // 106496

__global__ __launch_bounds__(512)
void k_mma_bn(const float* __restrict__ Y,
              const __half* __restrict__ Bf,
              float* __restrict__ Cf, int M,
              const float* __restrict__ stats_in, const float* __restrict__ gamma,
              const float* __restrict__ beta, float* __restrict__ stats_out) {
    constexpr int KTOT = 512, BN = 256, NB = 4, NC = 16;
    constexpr int O_B = 40960;
    constexpr int O_AFF = 102400;
    extern __shared__ __align__(16) char smem[];
    float* s_aff = (float*)(smem + O_AFF);
    const int tid = threadIdx.x;
    const int wid = tid >> 5, lane = tid & 31;
    const int wm = wid & 3, wn = wid >> 2;
    const int bm = blockIdx.x * 128, bn = blockIdx.y * BN;
    const unsigned sb = smem_u32(smem);

    if (tid < 512) {
        float inv = 1.f / (float)M;
        float m = stats_in[tid] * inv;
        float var = stats_in[512 + tid] * inv - m * m;
        float sc = gamma[tid] * rsqrtf(var + BN_EPS);
        s_aff[tid] = sc;
        s_aff[512 + tid] = beta[tid] - m * sc;
    }

    const int arow = tid >> 2, quad = tid & 3;
    const int grA = min(bm + arow, M - 1);

    ACC_INIT(NB)

#define BNG_LOADB(STG, K0)                                                     \
    {                                                                          \
        unsigned st = sb + O_B + (STG) * 20480;                                \
        _Pragma("unroll") for (int i = 0; i < 2; i++) {                        \
            int brow = arow + i * 128;                                         \
            unsigned bd = brow * 80 + quad * 16;                               \
            size_t ob = (size_t)(bn + brow) * KTOT + (K0) + quad * 8;          \
            cpasync16(st + bd, Bf + ob);                                       \
        }                                                                      \
    }
#define BNG_LDGA(K0)                                                           \
    {                                                                          \
        const float4* yp = (const float4*)(Y + (size_t)grA * KTOT + (K0) + quad * 8);\
        ya[0] = __ldg(yp); ya[1] = __ldg(yp + 1);                              \
    }

    float4 ya[2];
    BNG_LDGA(0);
    BNG_LOADB(0, 0);
    asm volatile("cp.async.commit_group;");
    BNG_LOADB(1, 32);
    asm volatile("cp.async.commit_group;");
    __syncthreads();  // s_aff visible

    for (int c = 0; c < NC; c++) {
        // STS A(c): affine + relu + exact fp16 split (stage c&1)
        {
            unsigned hi[4], lo[4];
            const int kb = c * 32 + quad * 8;
#pragma unroll
            for (int j = 0; j < 2; j++) {
                float4 y = ya[j];
                const int k = kb + j * 4;
                float x0 = fmaxf(y.x * s_aff[k + 0] + s_aff[512 + k + 0], 0.f);
                float x1 = fmaxf(y.y * s_aff[k + 1] + s_aff[512 + k + 1], 0.f);
                float x2 = fmaxf(y.z * s_aff[k + 2] + s_aff[512 + k + 2], 0.f);
                float x3 = fmaxf(y.w * s_aff[k + 3] + s_aff[512 + k + 3], 0.f);
                split2h(x0, x1, hi[j * 2], lo[j * 2]);
                split2h(x2, x3, hi[j * 2 + 1], lo[j * 2 + 1]);
            }
            char* ad = smem + (c & 1) * 20480 + arow * 80 + quad * 16;
            *(uint4*)ad = make_uint4(hi[0], hi[1], hi[2], hi[3]);
            *(uint4*)(ad + 10240) = make_uint4(lo[0], lo[1], lo[2], lo[3]);
        }
        asm volatile("cp.async.wait_group 1;");
        __syncthreads();
        if (c + 1 < NC) BNG_LDGA((c + 1) * 32);
        if (c + 2 < NC) BNG_LOADB((c + 2) % 3, (c + 2) * 32);
        asm volatile("cp.async.commit_group;");

        const unsigned ast = sb + (c & 1) * 20480;
        const unsigned bst = sb + O_B + (c % 3) * 20480;
#pragma unroll
        for (int ks = 0; ks < 2; ks++) {
            const unsigned koff = ks * 32;
            unsigned ah[2][4], al[2][4];
#pragma unroll
            for (int mf = 0; mf < 2; mf++) {
                unsigned addr = ast + (wm * 32 + mf * 16 + (lane & 15)) * 80 +
                                ((lane >> 4) * 16) + koff;
                ldm4(ah[mf], addr);
                ldm4(al[mf], addr + 10240);
            }
#pragma unroll
            for (int nb = 0; nb < NB; nb++) {
                unsigned addr = bst + (wn * 64 + nb * 16 + (lane & 15)) * 80 +
                                ((lane >> 4) * 16) + koff;
                unsigned bb[4];
                ldm4(bb, addr);
                unsigned b0[2] = {bb[0], bb[2]}, b1[2] = {bb[1], bb[3]};
                MMA8(nb, ah, al, b0, b1)
            }
        }
    }
#undef BNG_LOADB
#undef BNG_LDGA

    const int Nout = 512;
    EPILOGUE_STORE(256, Nout)
    EPILOGUE_STATS(256)
}

// ---------------- decoder final GEMM: fused edge loader, 2-pass fp16 ----------------
// A: 2 stages x 20480. B: 3 stages x 10240 at +40960.
#define DEC_SMEM (2 * 20480 + 3 * 10240)  // 71680

__global__ __launch_bounds__(512)
void k_dec(const float* __restrict__ PQ,
           const __half* __restrict__ Bf,
           float* __restrict__ Cf, int M,
           const int* __restrict__ gu, const int* __restrict__ gv,
           const float* __restrict__ bias1, const float* __restrict__ bias2) {
    constexpr int KTOT = 512, NB = 2, NC = 16;
    extern __shared__ __align__(16) char smem[];
    __shared__ int s_u[128], s_v[128];
    const int tid = threadIdx.x;
    const int wid = tid >> 5, lane = tid & 31;
    const int wm = wid & 3, wn = wid >> 2;
    const int bm = blockIdx.x * 128;
    const unsigned sb = smem_u32(smem);

    if (tid < 128) {
        int e = min(bm + tid, M - 1);
        s_u[tid] = gu[e];
        s_v[tid] = gv[e];
    }
    __syncthreads();

    const int arow = tid >> 2, quad = tid & 3;
    const size_t prow = (size_t)s_u[arow] * 1024;
    const size_t qrow = (size_t)s_v[arow] * 1024 + 512;

    ACC_INIT(NB)

#define DEC_LOADB(STG, K0)                                                     \
    {                                                                          \
        unsigned st = sb + 40960 + (STG) * 10240;                              \
        unsigned bd = arow * 80 + quad * 16;                                   \
        size_t ob = (size_t)arow * KTOT + (K0) + quad * 8;                     \
        cpasync16(st + bd, Bf + ob);                                           \
    }
#define DEC_LDGA(K0)                                                           \
    {                                                                          \
        const float4* pp = (const float4*)(PQ + prow + (K0) + quad * 8);       \
        const float4* qq = (const float4*)(PQ + qrow + (K0) + quad * 8);       \
        pa[0] = __ldg(pp); pa[1] = __ldg(pp + 1);                              \
        qa[0] = __ldg(qq); qa[1] = __ldg(qq + 1);                              \
    }

    float4 pa[2], qa[2];
    DEC_LDGA(0);
    DEC_LOADB(0, 0);
    asm volatile("cp.async.commit_group;");
    DEC_LOADB(1, 32);
    asm volatile("cp.async.commit_group;");

    for (int c = 0; c < NC; c++) {
        {
            unsigned hi[4], lo[4];
            const float* b1 = bias1 + c * 32 + quad * 8;
#pragma unroll
            for (int j = 0; j < 2; j++) {
                float4 p = pa[j], q = qa[j];
                float4 bb = *(const float4*)(b1 + j * 4);
                float x0 = fmaxf(p.x + q.x + bb.x, 0.f);
                float x1 = fmaxf(p.y + q.y + bb.y, 0.f);
                float x2 = fmaxf(p.z + q.z + bb.z, 0.f);
                float x3 = fmaxf(p.w + q.w + bb.w, 0.f);
                split2h(x0, x1, hi[j * 2], lo[j * 2]);
                split2h(x2, x3, hi[j * 2 + 1], lo[j * 2 + 1]);
            }
            char* ad = smem + (c & 1) * 20480 + arow * 80 + quad * 16;
            *(uint4*)ad = make_uint4(hi[0], hi[1], hi[2], hi[3]);
            *(uint4*)(ad + 10240) = make_uint4(lo[0], lo[1], lo[2], lo[3]);
        }
        asm volatile("cp.async.wait_group 1;");
        __syncthreads();
        if (c + 1 < NC) DEC_LDGA((c + 1) * 32);
        if (c + 2 < NC) DEC_LOADB((c + 2) % 3, (c + 2) * 32);
        asm volatile("cp.async.commit_group;");

        const unsigned ast = sb + (c & 1) * 20480;
        const unsigned bst = sb + 40960 + (c % 3) * 10240;
#pragma unroll
        for (int ks = 0; ks < 2; ks++) {
            const unsigned koff = ks * 32;
            unsigned ah[2][4], al[2][4];
#pragma unroll
            for (int mf = 0; mf < 2; mf++) {
                unsigned addr = ast + (wm * 32 + mf * 16 + (lane & 15)) * 80 +
                                ((lane >> 4) * 16) + koff;
                ldm4(ah[mf], addr);
                ldm4(al[mf], addr + 10240);
            }
#pragma unroll
            for (int nb = 0; nb < NB; nb++) {
                unsigned addr = bst + (wn * 32 + nb * 16 + (lane & 15)) * 80 +
                                ((lane >> 4) * 16) + koff;
                unsigned bb[4];
                ldm4(bb, addr);
                unsigned b0[2] = {bb[0], bb[2]}, b1[2] = {bb[1], bb[3]};
                MMA8(nb, ah, al, b0, b1)
            }
        }
    }
#undef DEC_LOADB
#undef DEC_LDGA

#pragma unroll
    for (int mf = 0; mf < 2; mf++) {
        const int r0 = bm + wm * 32 + mf * 16 + (lane >> 2);
#pragma unroll
        for (int nf = 0; nf < 2 * NB; nf++) {
            const int col = wn * 32 + nf * 8 + (lane & 3) * 2;
#pragma unroll
            for (int hh = 0; hh < 2; hh++) {
                const int row = r0 + hh * 8;
                if (row >= M) continue;
                float2 s = make_float2(acc[mf][nf][hh * 2] + bias2[col],
                                       acc[mf][nf][hh * 2 + 1] + bias2[col + 1]);
                *(float2*)(Cf + (size_t)row * OUTD + col) = s;
            }
        }
    }
}

// ---------------- CSR build ----------------
__global__ void k_zerodeg(int Nn) {
    int i = blockIdx.x * blockDim.x + threadIdx.x;
    if (i < Nn) g_deg[i] = 0;
}
__global__ void k_deg(const int* __restrict__ u, const int* __restrict__ v, int E) {
    int e = blockIdx.x * blockDim.x + threadIdx.x;
    if (e >= E) return;
    atomicAdd(&g_deg[u[e]], 1);
    atomicAdd(&g_deg[v[e]], 1);
}
__global__ void k_scan(int Nn) {
    __shared__ int warpsum[32];
    __shared__ int s_carry;
    const int tid = threadIdx.x, lane = tid & 31, w = tid >> 5;
    if (tid == 0) s_carry = 0;
    __syncthreads();
    for (int base = 0; base < Nn; base += 1024) {
        int i = base + tid;
        int v = (i < Nn) ? g_deg[i] : 0;
        int x = v;
#pragma unroll
        for (int o = 1; o < 32; o <<= 1) {
            int t = __shfl_up_sync(0xffffffffu, x, o);
            if (lane >= o) x += t;
        }
        if (lane == 31) warpsum[w] = x;
        __syncthreads();
        if (w == 0) {
            int s = warpsum[lane];
#pragma unroll
            for (int o = 1; o < 32; o <<= 1) {
                int t = __shfl_up_sync(0xffffffffu, s, o);
                if (lane >= o) s += t;
            }
            warpsum[lane] = s;
        }
        __syncthreads();
        int incl = x + (w > 0 ? warpsum[w - 1] : 0) + s_carry;
        if (i < Nn) {
            int excl = incl - v;
            g_off[i] = excl;
            g_cur[i] = excl;
        }
        __syncthreads();
        if (tid == 1023) s_carry = incl;
        __syncthreads();
    }
    if (tid == 0) g_off[Nn] = s_carry;
}
__global__ void k_fill(const int* __restrict__ u, const int* __restrict__ v, int E) {
    int e = blockIdx.x * blockDim.x + threadIdx.x;
    if (e >= E) return;
    int a = u[e], b = v[e];
    int p = atomicAdd(&g_cur[b], 1);
    g_adj[p] = a;
    int q = atomicAdd(&g_cur[a], 1);
    g_adj[q] = b;
}

// ---------------- aggregation: z = 2h + sum_{nb} h[nb] (h fp16 slot) -> fp16 pairs ----------------
// Block 0 also zeroes both BN stats slots (safe: runs strictly between the
// previous layer's stats read and this layer's GEMM1 stats write).
__global__ void k_agg(const __half* __restrict__ H, int Nn) {
    if (blockIdx.x == 0) {
#pragma unroll
        for (int t = threadIdx.x; t < 2048; t += 256) g_stats[t] = 0.f;
    }
    const int w = threadIdx.x >> 5;               // 0..7
    const int node = blockIdx.x * 4 + (w >> 1);
    if (node >= Nn) return;
    const int lane = threadIdx.x & 31;
    const int ci = (w & 1) * 32 + lane;           // uint4 index 0..63 (8 halves each)

    float acc[8];
    {
        uint4 t = ((const uint4*)(H + (size_t)node * D))[ci];
        const __half2* hh = (const __half2*)&t;
#pragma unroll
        for (int j = 0; j < 4; j++) {
            float2 f = __half22float2(hh[j]);
            acc[j * 2] = 2.f * f.x;
            acc[j * 2 + 1] = 2.f * f.y;
        }
    }
    const int e1 = g_off[node + 1];
    int e = g_off[node];
    if (e < e1) {
        uint4 cur = ((const uint4*)(H + (size_t)__ldg(&g_adj[e]) * D))[ci];
        for (++e; e < e1; ++e) {
            uint4 nxt = ((const uint4*)(H + (size_t)__ldg(&g_adj[e]) * D))[ci];
            const __half2* hh = (const __half2*)&cur;
#pragma unroll
            for (int j = 0; j < 4; j++) {
                float2 f = __half22float2(hh[j]);
                acc[j * 2] += f.x;
                acc[j * 2 + 1] += f.y;
            }
            cur = nxt;
        }
        const __half2* hh = (const __half2*)&cur;
#pragma unroll
        for (int j = 0; j < 4; j++) {
            float2 f = __half22float2(hh[j]);
            acc[j * 2] += f.x;
            acc[j * 2 + 1] += f.y;
        }
    }
    {
        unsigned hi[4], lo[4];
        split2h(acc[0], acc[1], hi[0], lo[0]);
        split2h(acc[2], acc[3], hi[1], lo[1]);
        split2h(acc[4], acc[5], hi[2], lo[2]);
        split2h(acc[6], acc[7], hi[3], lo[3]);
        size_t o = (size_t)node * D + (size_t)ci * 8;
        *(uint4*)(g_zh + o) = make_uint4(hi[0], hi[1], hi[2], hi[3]);
        *(uint4*)(g_zl + o) = make_uint4(lo[0], lo[1], lo[2], lo[3]);
    }
}

// ---------------- elementwise kernels ----------------
// h0 = emb[h_ids]  (fp16, slot 0 only — hidden_sum is computed lazily at the end)
__global__ void k_gather(const int* __restrict__ ids, const float* __restrict__ emb, int Nn) {
    int idx = blockIdx.x * blockDim.x + threadIdx.x;
    int row = idx >> 7;
    if (row >= Nn) return;
    int c = (idx & 127) << 2;
    float4 val = *(const float4*)(emb + (size_t)ids[row] * D + c);
    size_t o = (size_t)row * D + c;
    ((unsigned*)(g_hl + o))[0] = pack2h(val.x, val.y);
    ((unsigned*)(g_hl + o))[1] = pack2h(val.z, val.w);
}

// merged weight conversion: all matrices, one launch.
#define WCVT_TOTAL (1048576 + 1048576 + 524288 + 65536)
__global__ void k_wcvt(const float* __restrict__ lin1, const float* __restrict__ lin2,
                       const float* __restrict__ W1, const float* __restrict__ W2) {
    int idx = blockIdx.x * blockDim.x + threadIdx.x;
    if (idx >= WCVT_TOTAL) return;
    if (idx < 1048576) {
        int local = idx;
        int mi = local >> 18, within = local & 262143;
        int n = within >> 9, k = within & 511;
        g_l1f[idx] = __float2half(lin1[(size_t)mi * 262144 + (size_t)k * 512 + n]);
    } else if (idx < 2097152) {
        int local = idx - 1048576;
        int mi = local >> 18, within = local & 262143;
        int n = within >> 9, k = within & 511;
        g_l2f[local] = __float2half(lin2[(size_t)mi * 262144 + (size_t)k * 512 + n]);
    } else if (idx < 2621440) {
        int local = idx - 2097152;
        int half = local >> 18, within = local & 262143;
        int n = within >> 9, k = within & 511;
        g_w1f[local] = __float2half(W1[(size_t)half * 262144 + (size_t)k * 512 + n]);
    } else {
        int local = idx - 2621440;
        int n = local >> 9, k = local & 511;
        g_w2f[local] = __float2half(W2[(size_t)k * OUTD + n]);
    }
}

// h_out = relu(affine(Y2))  (fp16 slot; aff computed in-block from stats slot)
__global__ void k_bnrelu(const float* __restrict__ Y2,
                         const float* __restrict__ stats,
                         const float* __restrict__ gamma,
                         const float* __restrict__ beta,
                         __half* __restrict__ Hout, int Nn) {
    __shared__ float s_aff[1024];
    int tid = threadIdx.x;
    {
        float inv = 1.f / (float)Nn;
#pragma unroll
        for (int j = tid; j < 512; j += 256) {
            float m = stats[j] * inv;
            float var = stats[512 + j] * inv - m * m;
            float sc = gamma[j] * rsqrtf(var + BN_EPS);
            s_aff[j] = sc;
            s_aff[512 + j] = beta[j] - m * sc;
        }
    }
    __syncthreads();
    int idx = blockIdx.x * blockDim.x + tid;
    if (idx >= Nn * 128) return;
    int c = (idx & 127) << 2;
    float4 v = *(const float4*)(Y2 + (size_t)idx * 4);
    v.x = fmaxf(v.x * s_aff[c + 0] + s_aff[512 + c + 0], 0.f);
    v.y = fmaxf(v.y * s_aff[c + 1] + s_aff[512 + c + 1], 0.f);
    v.z = fmaxf(v.z * s_aff[c + 2] + s_aff[512 + c + 2], 0.f);
    v.w = fmaxf(v.w * s_aff[c + 3] + s_aff[512 + c + 3], 0.f);
    ((unsigned*)(Hout + (size_t)idx * 4))[0] = pack2h(v.x, v.y);
    ((unsigned*)(Hout + (size_t)idx * 4))[1] = pack2h(v.z, v.w);
}

// hidden_sum = sum of the 5 h slots -> fp16 pairs for decoder PQ GEMM
__global__ void k_hsum(int Nn) {
    int idx = blockIdx.x * blockDim.x + threadIdx.x;
    if (idx >= Nn * 64) return;  // each thread: one uint4 = 8 halves
    float acc[8];
#pragma unroll
    for (int j = 0; j < 8; j++) acc[j] = 0.f;
#pragma unroll
    for (int s = 0; s < 5; s++) {
        uint4 t = ((const uint4*)(g_hl + (size_t)s * ND))[idx];
        const __half2* hh = (const __half2*)&t;
#pragma unroll
        for (int j = 0; j < 4; j++) {
            float2 f = __half22float2(hh[j]);
            acc[j * 2] += f.x;
            acc[j * 2 + 1] += f.y;
        }
    }
    unsigned hi[4], lo[4];
    split2h(acc[0], acc[1], hi[0], lo[0]);
    split2h(acc[2], acc[3], hi[1], lo[1]);
    split2h(acc[4], acc[5], hi[2], lo[2]);
    split2h(acc[6], acc[7], hi[3], lo[3]);
    ((uint4*)g_hsfh)[idx] = make_uint4(hi[0], hi[1], hi[2], hi[3]);
    ((uint4*)g_hsfl)[idx] = make_uint4(lo[0], lo[1], lo[2], lo[3]);
}

// ---------------- launch ----------------
extern "C" void kernel_launch(void* const* d_in, const int* in_sizes, int n_in,
                              void* d_out, int out_size) {
    const int* h_ids = (const int*)d_in[0];
    const int* u     = (const int*)d_in[1];
    const int* v     = (const int*)d_in[2];
    const float* emb   = (const float*)d_in[3];
    const float* lin1  = (const float*)d_in[4];
    const float* lin2  = (const float*)d_in[5];
    const float* bn1_g = (const float*)d_in[6];
    const float* bn1_b = (const float*)d_in[7];
    const float* bn2_g = (const float*)d_in[8];
    const float* bn2_b = (const float*)d_in[9];
    const float* W1_w  = (const float*)d_in[10];
    const float* W1_b  = (const float*)d_in[11];
    const float* W2_w  = (const float*)d_in[12];
    const float* W2_b  = (const float*)d_in[13];
    float* out = (float*)d_out;

    const int N = in_sizes[0];
    const int E = in_sizes[1];
    const int L = in_sizes[4] / (D * D);

    static int s_attr = 0;
    if (!s_attr) {
        cudaFuncSetAttribute(k_mma_f16<0>, cudaFuncAttributeMaxDynamicSharedMemorySize, PQ_SMEM);
        cudaFuncSetAttribute(k_mma_f16<1>, cudaFuncAttributeMaxDynamicSharedMemorySize, PQ_SMEM);
        cudaFuncSetAttribute(k_mma_bn, cudaFuncAttributeMaxDynamicSharedMemorySize, BNG_SMEM);
        cudaFuncSetAttribute(k_dec, cudaFuncAttributeMaxDynamicSharedMemorySize, DEC_SMEM);
        s_attr = 1;
    }

    float *dg_z, *dg_y, *dg_pq, *dg_stats;
    cudaGetSymbolAddress((void**)&dg_z, g_z);
    cudaGetSymbolAddress((void**)&dg_y, g_y);
    cudaGetSymbolAddress((void**)&dg_pq, g_pq);
    cudaGetSymbolAddress((void**)&dg_stats, g_stats);
    __half *hl, *zh, *zl, *hsfh, *hsfl, *l1f, *l2f, *w1f, *w2f;
    cudaGetSymbolAddress((void**)&hl, g_hl);
    cudaGetSymbolAddress((void**)&zh, g_zh);  cudaGetSymbolAddress((void**)&zl, g_zl);
    cudaGetSymbolAddress((void**)&hsfh, g_hsfh); cudaGetSymbolAddress((void**)&hsfl, g_hsfl);
    cudaGetSymbolAddress((void**)&l1f, g_l1f);
    cudaGetSymbolAddress((void**)&l2f, g_l2f);
    cudaGetSymbolAddress((void**)&w1f, g_w1f);
    cudaGetSymbolAddress((void**)&w2f, g_w2f);

    const int ew = N * 128, ewB = (ew + 255) / 256;
    const int mtiles = (N + 127) / 128;
    const int etiles = (E + 127) / 128;
    const int edB = (E + 255) / 256;
    const int ndB = (N + 255) / 256;
    const int aggB = (N + 3) / 4;
    const int hsB = (N * 64 + 255) / 256;

    // merged weight conversion (one launch)
    k_wcvt<<<(WCVT_TOTAL + 255) / 256, 256>>>(lin1, lin2, W1_w, W2_w);

    // h0 = emb[h_ids] (fp16, slot 0)
    k_gather<<<ewB, 256>>>(h_ids, emb, N);

    // CSR build (once)
    k_zerodeg<<<ndB, 256>>>(N);
    k_deg<<<edB, 256>>>(u, v, E);
    k_scan<<<1, 1024>>>(N);
    k_fill<<<edB, 256>>>(u, v, E);

    for (int i = 0; i < L; i++) {
        // z = 2h + neighbor sums -> fp16 pairs ; block 0 zeroes both stats slots
        k_agg<<<aggB, 256>>>(hl + (size_t)i * ND, N);
        // y = z @ lin1[i]  (2-pass fp16, stats -> slot0)
        k_mma_f16<1><<<dim3(mtiles, 2), 512, PQ_SMEM>>>(
            zh, zl, l1f + (size_t)i * D * D, dg_y, N, D, dg_stats);
        // z(out) = relu(bn1(y)) @ lin2[i]  (fused BN loader, 2-pass fp16; stats -> slot1)
        k_mma_bn<<<dim3(mtiles, 2), 512, BNG_SMEM>>>(
            dg_y, l2f + (size_t)i * D * D, dg_z, N,
            dg_stats, bn1_g + (size_t)i * D, bn1_b + (size_t)i * D,
            dg_stats + 1024);
        // h_{i+1} = relu(bn2(z))  (fp16 slot i+1; aff computed in-block from slot1)
        k_bnrelu<<<ewB, 256>>>(dg_z, dg_stats + 1024,
            bn2_g + (size_t)i * D, bn2_b + (size_t)i * D,
            hl + (size_t)(i + 1) * ND, N);
    }

    // hidden_sum = sum of 5 h slots -> fp16 pairs
    k_hsum<<<hsB, 256>>>(N);
    // decoder: [P|Q] = hsum_fp16pairs @ fp16(W1t)^T  (2-pass fp16, Nout=1024)
    k_mma_f16<0><<<dim3(mtiles, 4), 512, PQ_SMEM>>>(
        hsfh, hsfl, w1f, dg_pq, N, 2 * D, nullptr);
    // out = relu(P[u]+Q[v]+b1) @ fp16(W2)^T + b2  (fused edge loader, 2-pass fp16)
    k_dec<<<etiles, 512, DEC_SMEM>>>(dg_pq, w2f, out, E, u, v, W1_b, W2_b);
}